// round 3
// baseline (speedup 1.0000x reference)
#include <cuda_runtime.h>

#define NNODE 50000
#define NEDGE 800000

// ---------------- device scratch (allocation-free, 16B-aligned for vector ops) ----------------
__device__ int   g_rowptr[NNODE + 1];
__device__ int   g_fill[NNODE];
__device__ int   g_col[NEDGE];
__device__ float g_deginv[NNODE];
__device__ __align__(16) float g_inp[(size_t)NNODE * 128];   // pre-relu input embedding (residual src)
__device__ __align__(16) float g_bufA[(size_t)NNODE * 128];
__device__ __align__(16) float g_bufB[(size_t)NNODE * 128];
__device__ __align__(16) float g_agg[(size_t)NNODE * 128];

__device__ __forceinline__ int clampN(int v) {
    return min(max(v, 0), NNODE - 1);
}

// ---------------- f32x2 packed-FMA helpers (ptxas won't emit these itself) ----------------
__device__ __forceinline__ unsigned long long pack2(float lo, float hi) {
    unsigned long long r;
    asm("mov.b64 %0, {%1, %2};" : "=l"(r) : "f"(lo), "f"(hi));
    return r;
}
__device__ __forceinline__ void unpack2(unsigned long long v, float& lo, float& hi) {
    asm("mov.b64 {%0, %1}, %2;" : "=f"(lo), "=f"(hi) : "l"(v));
}
__device__ __forceinline__ void ffma2(unsigned long long& d, unsigned long long a,
                                      unsigned long long b) {
    asm("fma.rn.f32x2 %0, %1, %2, %0;" : "+l"(d) : "l"(a), "l"(b));
}

// ---------------- CSR build ----------------
__global__ void k_zero_fill() {
    int i = blockIdx.x * blockDim.x + threadIdx.x;
    if (i < NNODE) g_fill[i] = 0;
}

// edge_index is int32 (JAX default x64-disabled demotes int64): row 0 = src, row 1 = dst
__global__ void k_hist(const int* __restrict__ ei) {
    int e = blockIdx.x * blockDim.x + threadIdx.x;
    if (e < NEDGE) atomicAdd(&g_fill[clampN(ei[NEDGE + e])], 1);
}

// Single-block exclusive scan over 50000 degrees; also writes deginv and rowptr.
__global__ void __launch_bounds__(1024) k_scan() {
    const int t = threadIdx.x;
    __shared__ int wsum[32];
    __shared__ int s_total;
    __shared__ int s_carry;
    if (t == 0) s_carry = 0;
    __syncthreads();
    for (int base = 0; base < NNODE; base += 1024) {
        int i = base + t;
        int v = (i < NNODE) ? g_fill[i] : 0;
        int inc = v;
#pragma unroll
        for (int o = 1; o < 32; o <<= 1) {
            int y = __shfl_up_sync(0xffffffffu, inc, o);
            if ((t & 31) >= o) inc += y;
        }
        if ((t & 31) == 31) wsum[t >> 5] = inc;
        __syncthreads();
        if (t < 32) {
            int wv = wsum[t];
            int winc = wv;
#pragma unroll
            for (int o = 1; o < 32; o <<= 1) {
                int y = __shfl_up_sync(0xffffffffu, winc, o);
                if (t >= o) winc += y;
            }
            wsum[t] = winc - wv;   // exclusive warp base
            if (t == 31) s_total = winc;
        }
        __syncthreads();
        int excl = inc - v + wsum[t >> 5] + s_carry;
        if (i < NNODE) {
            g_rowptr[i] = excl;
            g_fill[i]   = excl;
            g_deginv[i] = 1.0f / (float)max(v, 1);
        }
        __syncthreads();
        if (t == 0) s_carry += s_total;
        __syncthreads();
    }
    if (t == 0) g_rowptr[NNODE] = s_carry;
}

__global__ void k_csr_fill(const int* __restrict__ ei) {
    int e = blockIdx.x * blockDim.x + threadIdx.x;
    if (e < NEDGE) {
        int dstn = clampN(ei[NEDGE + e]);
        int pos  = atomicAdd(&g_fill[dstn], 1);
        if (pos >= 0 && pos < NEDGE) g_col[pos] = clampN(ei[e]);
    }
}

// ---------------- mean aggregation: one warp per node, float4 lanes ----------------
// sel=0: src = g_bufA, sel=1: src = g_bufB. Writes g_agg.
__global__ void __launch_bounds__(256) k_agg(int sel) {
    int w = (blockIdx.x * blockDim.x + threadIdx.x) >> 5;
    if (w >= NNODE) return;
    const float* __restrict__ src = sel ? g_bufB : g_bufA;
    int lane = threadIdx.x & 31;
    int beg = g_rowptr[w], end = g_rowptr[w + 1];
    float ax = 0.f, ay = 0.f, az = 0.f, aw = 0.f;
    int i = beg;
    for (; i + 1 < end; i += 2) {   // MLP=2
        int s0 = g_col[i], s1 = g_col[i + 1];
        float4 a = __ldg((const float4*)(src + (size_t)s0 * 128 + lane * 4));
        float4 b = __ldg((const float4*)(src + (size_t)s1 * 128 + lane * 4));
        ax += a.x + b.x; ay += a.y + b.y; az += a.z + b.z; aw += a.w + b.w;
    }
    if (i < end) {
        int s0 = g_col[i];
        float4 a = __ldg((const float4*)(src + (size_t)s0 * 128 + lane * 4));
        ax += a.x; ay += a.y; az += a.z; aw += a.w;
    }
    float d = g_deginv[w];
    float4 o = make_float4(ax * d, ay * d, az * d, aw * d);
    *(float4*)(g_agg + (size_t)w * 128 + lane * 4) = o;
}

// ---------------- dual-input GEMM with fused epilogue ----------------
// MODE 0: A1=Aext(x);   g_bufA=relu(v), g_inp=v            (input embedding)
// MODE 1: A1=g_agg, A2=sel?bufB:bufA; out=sel?bufA:bufB = relu(v)+0.2*g_inp
// MODE 2: A1=g_agg, A2=g_bufA;        outExt = v           (final, OUTC=64)
template <int OUTC, int MODE>
__global__ void __launch_bounds__(256) k_gemm(
    const float* __restrict__ Aext, const float* __restrict__ W1,
    const float* __restrict__ W2, const float* __restrict__ bias,
    float* __restrict__ outExt, int sel) {
    constexpr int CPT = OUTC / 16;   // cols per thread (8 or 4)
    constexpr int NP  = CPT / 2;     // f32x2 pairs per thread (4 or 2)

    __shared__ __align__(16) float As[64][33];
    __shared__ __align__(16) float Ws[32][OUTC];

    const float* A1;
    const float* A2 = nullptr;
    float* outp;
    if (MODE == 0) {
        A1 = Aext; outp = g_bufA;
    } else if (MODE == 1) {
        A1 = g_agg; A2 = sel ? g_bufB : g_bufA; outp = sel ? g_bufA : g_bufB;
    } else {
        A1 = g_agg; A2 = g_bufA; outp = outExt;
    }

    const int t   = threadIdx.x;
    const int cx  = t & 15;
    const int ry  = t >> 4;
    const int row0 = blockIdx.x * 64;

    unsigned long long acc[4][NP];
#pragma unroll
    for (int r = 0; r < 4; r++)
#pragma unroll
        for (int p = 0; p < NP; p++) acc[r][p] = 0ull;

    constexpr int nsrc = (MODE == 0) ? 1 : 2;
#pragma unroll
    for (int s = 0; s < nsrc; s++) {
        const float* A = s ? A2 : A1;
        const float* W = s ? W2 : W1;
        for (int ks = 0; ks < 128; ks += 32) {
            for (int idx = t; idx < 64 * 32; idx += 256) {
                int r = idx >> 5, c = idx & 31;
                int gr = row0 + r;
                As[r][c] = (gr < NNODE) ? A[(size_t)gr * 128 + ks + c] : 0.f;
            }
            for (int idx = t; idx < 32 * OUTC; idx += 256) {
                int r = idx / OUTC, c = idx % OUTC;
                Ws[r][c] = W[(size_t)(ks + r) * OUTC + c];
            }
            __syncthreads();
#pragma unroll 8
            for (int kk = 0; kk < 32; kk++) {
                unsigned long long ap[4];
#pragma unroll
                for (int r = 0; r < 4; r++) {
                    float a = As[ry * 4 + r][kk];
                    ap[r] = pack2(a, a);
                }
                unsigned long long wv[NP];
                const ulonglong2* wp =
                    reinterpret_cast<const ulonglong2*>(&Ws[kk][cx * CPT]);
                if constexpr (NP == 4) {
                    ulonglong2 w0 = wp[0], w1 = wp[1];
                    wv[0] = w0.x; wv[1] = w0.y; wv[2] = w1.x; wv[3] = w1.y;
                } else {
                    ulonglong2 w0 = wp[0];
                    wv[0] = w0.x; wv[1] = w0.y;
                }
#pragma unroll
                for (int r = 0; r < 4; r++)
#pragma unroll
                    for (int p = 0; p < NP; p++) ffma2(acc[r][p], ap[r], wv[p]);
            }
            __syncthreads();
        }
    }

#pragma unroll
    for (int r = 0; r < 4; r++) {
        int gr = row0 + ry * 4 + r;
        if (gr >= NNODE) continue;
#pragma unroll
        for (int p = 0; p < NP; p++) {
            int gc = cx * CPT + 2 * p;
            float lo, hi;
            unpack2(acc[r][p], lo, hi);
            float v0 = lo + bias[gc];
            float v1 = hi + bias[gc + 1];
            size_t o = (size_t)gr * OUTC + gc;
            if constexpr (MODE == 0) {
                g_inp[o]     = v0;
                g_inp[o + 1] = v1;
                outp[o]      = fmaxf(v0, 0.f);
                outp[o + 1]  = fmaxf(v1, 0.f);
            } else if constexpr (MODE == 1) {
                outp[o]     = fmaxf(v0, 0.f) + 0.2f * g_inp[o];
                outp[o + 1] = fmaxf(v1, 0.f) + 0.2f * g_inp[o + 1];
            } else {
                outp[o]     = v0;
                outp[o + 1] = v1;
            }
        }
    }
}

// ---------------- row-wise log_softmax over 64 cols, one warp/row ----------------
__global__ void __launch_bounds__(256) k_lsm(float* __restrict__ o) {
    int row = (blockIdx.x * blockDim.x + threadIdx.x) >> 5;
    if (row >= NNODE) return;
    int lane = threadIdx.x & 31;
    float2 v = *(float2*)(o + (size_t)row * 64 + lane * 2);
    float m = fmaxf(v.x, v.y);
#pragma unroll
    for (int s = 16; s; s >>= 1) m = fmaxf(m, __shfl_xor_sync(0xffffffffu, m, s));
    float e = expf(v.x - m) + expf(v.y - m);
#pragma unroll
    for (int s = 16; s; s >>= 1) e += __shfl_xor_sync(0xffffffffu, e, s);
    float l = m + logf(e);
    v.x -= l;
    v.y -= l;
    *(float2*)(o + (size_t)row * 64 + lane * 2) = v;
}

// ---------------- launcher (kernel launches ONLY — graph-capture safe) ----------------
extern "C" void kernel_launch(void* const* d_in, const int* in_sizes, int n_in,
                              void* d_out, int out_size) {
    const float* x    = (const float*)d_in[0];
    const int*   ei   = (const int*)d_in[1];     // int32! (JAX demotes int64)
    const float* w_in = (const float*)d_in[2];
    const float* b_in = (const float*)d_in[3];
    const float* w_l0 = (const float*)d_in[4];
    const float* w_r0 = (const float*)d_in[5];
    const float* b0   = (const float*)d_in[6];
    const float* w_l1 = (const float*)d_in[7];
    const float* w_r1 = (const float*)d_in[8];
    const float* b1   = (const float*)d_in[9];
    const float* w_l2 = (const float*)d_in[10];
    const float* w_r2 = (const float*)d_in[11];
    const float* b2   = (const float*)d_in[12];
    float* out = (float*)d_out;

    const int GEMM_BLOCKS = (NNODE + 63) / 64;        // 782
    const int EDGE_BLOCKS = (NEDGE + 255) / 256;      // 3125
    const int WARP_BLOCKS = (NNODE * 32 + 255) / 256; // 6250

    // CSR build
    k_zero_fill<<<(NNODE + 255) / 256, 256>>>();
    k_hist<<<EDGE_BLOCKS, 256>>>(ei);
    k_scan<<<1, 1024>>>();
    k_csr_fill<<<EDGE_BLOCKS, 256>>>(ei);

    // input embedding: g_inp = x@w_in + b_in ; g_bufA = relu(g_inp)
    k_gemm<128, 0><<<GEMM_BLOCKS, 256>>>(x, w_in, nullptr, b_in, nullptr, 0);
    // layer 0: agg(bufA) -> gemm -> bufB
    k_agg<<<WARP_BLOCKS, 256>>>(0);
    k_gemm<128, 1><<<GEMM_BLOCKS, 256>>>(nullptr, w_l0, w_r0, b0, nullptr, 0);
    // layer 1: agg(bufB) -> gemm -> bufA
    k_agg<<<WARP_BLOCKS, 256>>>(1);
    k_gemm<128, 1><<<GEMM_BLOCKS, 256>>>(nullptr, w_l1, w_r1, b1, nullptr, 1);
    // layer 2: agg(bufA) -> gemm -> d_out [N,64]
    k_agg<<<WARP_BLOCKS, 256>>>(0);
    k_gemm<64, 2><<<GEMM_BLOCKS, 256>>>(nullptr, w_l2, w_r2, b2, out, 0);
    // log_softmax in place
    k_lsm<<<WARP_BLOCKS, 256>>>(out);
}

// round 4
// speedup vs baseline: 1.6561x; 1.6561x over previous
#include <cuda_runtime.h>

#define NNODE 50000
#define NEDGE 800000

// ---------------- device scratch (allocation-free, 16B-aligned) ----------------
__device__ int   g_rowptr[NNODE + 1];
__device__ int   g_fill[NNODE];
__device__ int   g_col[NEDGE];
__device__ float g_deginv[NNODE];
__device__ __align__(16) float g_inp[(size_t)NNODE * 128];   // pre-relu input embedding
__device__ __align__(16) float g_bufA[(size_t)NNODE * 128];
__device__ __align__(16) float g_bufB[(size_t)NNODE * 128];
__device__ __align__(16) float g_agg[(size_t)NNODE * 128];   // also reused as N x 64 "p" buffer

__device__ __forceinline__ int clampN(int v) { return min(max(v, 0), NNODE - 1); }

__device__ __forceinline__ unsigned f2tf32(float f) {
    unsigned u;
    asm("cvt.rna.tf32.f32 %0, %1;" : "=r"(u) : "f"(f));
    return u;
}

__device__ __forceinline__ void mma_tf32(float* c, const unsigned* a, unsigned b0,
                                         unsigned b1) {
    asm volatile(
        "mma.sync.aligned.m16n8k8.row.col.f32.tf32.tf32.f32 "
        "{%0,%1,%2,%3}, {%4,%5,%6,%7}, {%8,%9}, {%0,%1,%2,%3};"
        : "+f"(c[0]), "+f"(c[1]), "+f"(c[2]), "+f"(c[3])
        : "r"(a[0]), "r"(a[1]), "r"(a[2]), "r"(a[3]), "r"(b0), "r"(b1));
}

// ---------------- CSR build ----------------
__global__ void k_zero_fill() {
    int i = blockIdx.x * blockDim.x + threadIdx.x;
    if (i < NNODE) g_fill[i] = 0;
}

__global__ void k_hist(const int* __restrict__ ei) {
    int e = blockIdx.x * blockDim.x + threadIdx.x;
    if (e < NEDGE) atomicAdd(&g_fill[clampN(ei[NEDGE + e])], 1);
}

__global__ void __launch_bounds__(1024) k_scan() {
    const int t = threadIdx.x;
    __shared__ int wsum[32];
    __shared__ int s_total;
    __shared__ int s_carry;
    if (t == 0) s_carry = 0;
    __syncthreads();
    for (int base = 0; base < NNODE; base += 1024) {
        int i = base + t;
        int v = (i < NNODE) ? g_fill[i] : 0;
        int inc = v;
#pragma unroll
        for (int o = 1; o < 32; o <<= 1) {
            int y = __shfl_up_sync(0xffffffffu, inc, o);
            if ((t & 31) >= o) inc += y;
        }
        if ((t & 31) == 31) wsum[t >> 5] = inc;
        __syncthreads();
        if (t < 32) {
            int wv = wsum[t];
            int winc = wv;
#pragma unroll
            for (int o = 1; o < 32; o <<= 1) {
                int y = __shfl_up_sync(0xffffffffu, winc, o);
                if (t >= o) winc += y;
            }
            wsum[t] = winc - wv;
            if (t == 31) s_total = winc;
        }
        __syncthreads();
        int excl = inc - v + wsum[t >> 5] + s_carry;
        if (i < NNODE) {
            g_rowptr[i] = excl;
            g_fill[i]   = excl;
            g_deginv[i] = 1.0f / (float)max(v, 1);
        }
        __syncthreads();
        if (t == 0) s_carry += s_total;
        __syncthreads();
    }
    if (t == 0) g_rowptr[NNODE] = s_carry;
}

__global__ void k_csr_fill(const int* __restrict__ ei) {
    int e = blockIdx.x * blockDim.x + threadIdx.x;
    if (e < NEDGE) {
        int dstn = clampN(ei[NEDGE + e]);
        int pos  = atomicAdd(&g_fill[dstn], 1);
        if (pos >= 0 && pos < NEDGE) g_col[pos] = clampN(ei[e]);
    }
}

// ---------------- mean aggregation (128-dim): warp/node, float4 lanes, x4 unroll ----
__global__ void __launch_bounds__(256) k_agg(int sel) {
    int w = (blockIdx.x * blockDim.x + threadIdx.x) >> 5;
    if (w >= NNODE) return;
    const float* __restrict__ src = sel ? g_bufB : g_bufA;
    int lane = threadIdx.x & 31;
    int beg = g_rowptr[w], end = g_rowptr[w + 1];
    float ax = 0.f, ay = 0.f, az = 0.f, aw = 0.f;
    int i = beg;
    for (; i + 3 < end; i += 4) {
        int s0 = g_col[i], s1 = g_col[i + 1], s2 = g_col[i + 2], s3 = g_col[i + 3];
        float4 a = __ldg((const float4*)(src + (size_t)s0 * 128 + lane * 4));
        float4 b = __ldg((const float4*)(src + (size_t)s1 * 128 + lane * 4));
        float4 c = __ldg((const float4*)(src + (size_t)s2 * 128 + lane * 4));
        float4 d = __ldg((const float4*)(src + (size_t)s3 * 128 + lane * 4));
        ax += (a.x + b.x) + (c.x + d.x);
        ay += (a.y + b.y) + (c.y + d.y);
        az += (a.z + b.z) + (c.z + d.z);
        aw += (a.w + b.w) + (c.w + d.w);
    }
    for (; i < end; i++) {
        int s0 = g_col[i];
        float4 a = __ldg((const float4*)(src + (size_t)s0 * 128 + lane * 4));
        ax += a.x; ay += a.y; az += a.z; aw += a.w;
    }
    float d = g_deginv[w];
    float4 o = make_float4(ax * d, ay * d, az * d, aw * d);
    *(float4*)(g_agg + (size_t)w * 128 + lane * 4) = o;
}

// ---------------- tf32 tensor-core GEMM with fused epilogues ----------------
// 256 threads = 8 warps; warp tile 32x32; block tile BM x OUTC.
// MODE 0: A=x;                 g_inp = v;  g_bufA = relu(v)          (OUTC=128, BM=64)
// MODE 1: A1=g_agg, A2=h(sel); out(sel) = relu(v) + 0.2*g_inp       (OUTC=128, BM=64)
// MODE 2: A=g_bufA, dual B:    g_agg(p) = A@W1 ; out(q) = A@W2 + b  (OUTC=64,  BM=128)
template <int BM, int OUTC, int MODE>
__global__ void __launch_bounds__(256) k_mma(
    const float* __restrict__ Aext, const float* __restrict__ W1,
    const float* __restrict__ W2, const float* __restrict__ bias,
    float* __restrict__ outExt, int sel) {
    constexpr int WARPS_N = OUTC / 32;           // 4 or 2
    constexpr int WPAD = OUTC + 8;

    __shared__ unsigned As[BM][36];
    __shared__ unsigned Ws[32][WPAD];
    __shared__ unsigned Ws2[(MODE == 2) ? 32 : 1][(MODE == 2) ? WPAD : 1];

    const int t    = threadIdx.x;
    const int lane = t & 31;
    const int wid  = t >> 5;
    const int wm   = wid / WARPS_N;
    const int wn   = wid % WARPS_N;
    const int mBase = wm * 32;
    const int nBase = wn * 32;
    const int row0  = blockIdx.x * BM;
    const int tg4   = lane >> 2;
    const int t4    = lane & 3;

    const float* A1;
    const float* A2 = nullptr;
    float* outp;
    if (MODE == 0) {
        A1 = Aext; outp = g_bufA;
    } else if (MODE == 1) {
        A1 = g_agg; A2 = sel ? g_bufB : g_bufA; outp = sel ? g_bufA : g_bufB;
    } else {
        A1 = g_bufA; outp = outExt;
    }

    float c[2][4][4];
    float c2[(MODE == 2) ? 2 : 1][(MODE == 2) ? 4 : 1][(MODE == 2) ? 4 : 1];
#pragma unroll
    for (int mt = 0; mt < 2; mt++)
#pragma unroll
        for (int nt = 0; nt < 4; nt++)
#pragma unroll
            for (int i = 0; i < 4; i++) {
                c[mt][nt][i] = 0.f;
                if constexpr (MODE == 2) c2[mt][nt][i] = 0.f;
            }

    constexpr int nsrc = (MODE == 1) ? 2 : 1;
#pragma unroll
    for (int s = 0; s < nsrc; s++) {
        const float* A = (s == 0) ? A1 : A2;
        const float* W = (s == 0) ? W1 : W2;
        for (int kc = 0; kc < 4; kc++) {
            // load + convert A tile (BM x 32)
            for (int idx = t; idx < BM * 32; idx += 256) {
                int r = idx >> 5, cc = idx & 31;
                int gr = row0 + r;
                float fv = (gr < NNODE) ? A[(size_t)gr * 128 + kc * 32 + cc] : 0.f;
                As[r][cc] = f2tf32(fv);
            }
            // load + convert B tile(s) (32 x OUTC)
            for (int idx = t; idx < 32 * OUTC; idx += 256) {
                int r = idx / OUTC, cc = idx % OUTC;
                Ws[r][cc] = f2tf32(W[(size_t)(kc * 32 + r) * OUTC + cc]);
                if constexpr (MODE == 2)
                    Ws2[r][cc] = f2tf32(W2[(size_t)(kc * 32 + r) * OUTC + cc]);
            }
            __syncthreads();
#pragma unroll
            for (int ks = 0; ks < 4; ks++) {
                unsigned a[2][4];
#pragma unroll
                for (int mt = 0; mt < 2; mt++) {
                    int r = mBase + mt * 16 + tg4;
                    int cc = ks * 8 + t4;
                    a[mt][0] = As[r][cc];
                    a[mt][1] = As[r + 8][cc];
                    a[mt][2] = As[r][cc + 4];
                    a[mt][3] = As[r + 8][cc + 4];
                }
#pragma unroll
                for (int nt = 0; nt < 4; nt++) {
                    int kr = ks * 8 + t4;
                    int cn = nBase + nt * 8 + tg4;
                    unsigned b0 = Ws[kr][cn], b1 = Ws[kr + 4][cn];
#pragma unroll
                    for (int mt = 0; mt < 2; mt++) mma_tf32(c[mt][nt], a[mt], b0, b1);
                    if constexpr (MODE == 2) {
                        unsigned d0 = Ws2[kr][cn], d1 = Ws2[kr + 4][cn];
#pragma unroll
                        for (int mt = 0; mt < 2; mt++)
                            mma_tf32(c2[mt][nt], a[mt], d0, d1);
                    }
                }
            }
            __syncthreads();
        }
    }

    // epilogue
#pragma unroll
    for (int mt = 0; mt < 2; mt++) {
#pragma unroll
        for (int nt = 0; nt < 4; nt++) {
            int gc = nBase + nt * 8 + 2 * t4;
            float b0 = bias ? bias[gc] : 0.f;
            float b1 = bias ? bias[gc + 1] : 0.f;
#pragma unroll
            for (int half = 0; half < 2; half++) {
                int gr = row0 + mBase + mt * 16 + tg4 + half * 8;
                if (gr >= NNODE) continue;
                float v0 = c[mt][nt][half * 2] ;
                float v1 = c[mt][nt][half * 2 + 1];
                size_t o = (size_t)gr * OUTC + gc;
                if constexpr (MODE == 0) {
                    v0 += b0; v1 += b1;
                    *(float2*)(g_inp + o) = make_float2(v0, v1);
                    *(float2*)(outp + o) = make_float2(fmaxf(v0, 0.f), fmaxf(v1, 0.f));
                } else if constexpr (MODE == 1) {
                    v0 += b0; v1 += b1;
                    float2 rin = *(const float2*)(g_inp + o);
                    *(float2*)(outp + o) = make_float2(
                        fmaxf(v0, 0.f) + 0.2f * rin.x, fmaxf(v1, 0.f) + 0.2f * rin.y);
                } else {
                    // p = A@W1 (no bias) -> g_agg ; q = A@W2 + b -> out
                    *(float2*)(g_agg + o) = make_float2(v0, v1);
                    float q0 = c2[mt][nt][half * 2] + b0;
                    float q1 = c2[mt][nt][half * 2 + 1] + b1;
                    *(float2*)(outp + o) = make_float2(q0, q1);
                }
            }
        }
    }
}

// ---------------- final: mean-agg of p (64-dim) + q, fused log_softmax ----------------
__global__ void __launch_bounds__(256) k_agg64_lsm(float* __restrict__ out) {
    int w = (blockIdx.x * blockDim.x + threadIdx.x) >> 5;
    if (w >= NNODE) return;
    const float* __restrict__ p = g_agg;   // N x 64
    int lane = threadIdx.x & 31;
    int beg = g_rowptr[w], end = g_rowptr[w + 1];
    float ax = 0.f, ay = 0.f;
    int i = beg;
    for (; i + 3 < end; i += 4) {
        int s0 = g_col[i], s1 = g_col[i + 1], s2 = g_col[i + 2], s3 = g_col[i + 3];
        float2 a = __ldg((const float2*)(p + (size_t)s0 * 64 + lane * 2));
        float2 b = __ldg((const float2*)(p + (size_t)s1 * 64 + lane * 2));
        float2 cc = __ldg((const float2*)(p + (size_t)s2 * 64 + lane * 2));
        float2 d = __ldg((const float2*)(p + (size_t)s3 * 64 + lane * 2));
        ax += (a.x + b.x) + (cc.x + d.x);
        ay += (a.y + b.y) + (cc.y + d.y);
    }
    for (; i < end; i++) {
        int s0 = g_col[i];
        float2 a = __ldg((const float2*)(p + (size_t)s0 * 64 + lane * 2));
        ax += a.x; ay += a.y;
    }
    float d = g_deginv[w];
    float2 q = *(float2*)(out + (size_t)w * 64 + lane * 2);
    float v0 = q.x + ax * d;
    float v1 = q.y + ay * d;
    // log_softmax over the warp's 64 values
    float m = fmaxf(v0, v1);
#pragma unroll
    for (int s = 16; s; s >>= 1) m = fmaxf(m, __shfl_xor_sync(0xffffffffu, m, s));
    float e = expf(v0 - m) + expf(v1 - m);
#pragma unroll
    for (int s = 16; s; s >>= 1) e += __shfl_xor_sync(0xffffffffu, e, s);
    float l = m + logf(e);
    *(float2*)(out + (size_t)w * 64 + lane * 2) = make_float2(v0 - l, v1 - l);
}

// ---------------- launcher (kernel launches ONLY — graph-capture safe) ----------------
extern "C" void kernel_launch(void* const* d_in, const int* in_sizes, int n_in,
                              void* d_out, int out_size) {
    const float* x    = (const float*)d_in[0];
    const int*   ei   = (const int*)d_in[1];     // int32 (JAX demotes int64)
    const float* w_in = (const float*)d_in[2];
    const float* b_in = (const float*)d_in[3];
    const float* w_l0 = (const float*)d_in[4];
    const float* w_r0 = (const float*)d_in[5];
    const float* b0   = (const float*)d_in[6];
    const float* w_l1 = (const float*)d_in[7];
    const float* w_r1 = (const float*)d_in[8];
    const float* b1   = (const float*)d_in[9];
    const float* w_l2 = (const float*)d_in[10];
    const float* w_r2 = (const float*)d_in[11];
    const float* b2   = (const float*)d_in[12];
    float* out = (float*)d_out;

    const int GB64  = (NNODE + 63) / 64;          // 782
    const int GB128 = (NNODE + 127) / 128;        // 391
    const int EDGE_BLOCKS = (NEDGE + 255) / 256;  // 3125
    const int WARP_BLOCKS = (NNODE * 32 + 255) / 256;

    // CSR build
    k_zero_fill<<<(NNODE + 255) / 256, 256>>>();
    k_hist<<<EDGE_BLOCKS, 256>>>(ei);
    k_scan<<<1, 1024>>>();
    k_csr_fill<<<EDGE_BLOCKS, 256>>>(ei);

    // input embedding: g_inp = x@w_in + b_in ; g_bufA = relu(g_inp)
    k_mma<64, 128, 0><<<GB64, 256>>>(x, w_in, nullptr, b_in, nullptr, 0);
    // layer 0: agg(bufA) -> gemm -> bufB
    k_agg<<<WARP_BLOCKS, 256>>>(0);
    k_mma<64, 128, 1><<<GB64, 256>>>(nullptr, w_l0, w_r0, b0, nullptr, 0);
    // layer 1: agg(bufB) -> gemm -> bufA
    k_agg<<<WARP_BLOCKS, 256>>>(1);
    k_mma<64, 128, 1><<<GB64, 256>>>(nullptr, w_l1, w_r1, b1, nullptr, 1);
    // layer 2: p = bufA@w_l2 -> g_agg(Nx64); q = bufA@w_r2 + b2 -> out
    k_mma<128, 64, 2><<<GB128, 256>>>(nullptr, w_l2, w_r2, b2, out, 0);
    // out = log_softmax(q + mean_agg(p))
    k_agg64_lsm<<<WARP_BLOCKS, 256>>>(out);
}